// round 8
// baseline (speedup 1.0000x reference)
#include <cuda_runtime.h>
#include <cuda_bf16.h>
#include <cuda_fp16.h>
#include <cstdint>

#define NUM_AUTHOR 16604
#define NUM_NODES  29059
#define EMBED_DIM  300
#define BATCH      32768
#define KPAD       960        // 900 padded to 15 chunks of 64
#define NPAD       320        // 300 padded
#define NCHUNK     15
#define HROW       304        // fp16 table row stride (38 x uint4)

// stage byte offsets (SW128 swizzled, 128B rows, all 1024-aligned)
#define ST_AHI 0              // 128 x 128B = 16384
#define ST_ALO 16384
#define ST_BHI 32768          // 160 x 128B = 20480
#define ST_BLO 53248
#define ST_SIZE 73728         // 72 KB per stage

// ---------------- device scratch (allocation-free rule: __device__ globals) ---
__device__ int g_seg_start[BATCH + 1];
__device__ __align__(16) __nv_bfloat16 g_Ahi[(size_t)BATCH * KPAD];
__device__ __align__(16) __nv_bfloat16 g_Alo[(size_t)BATCH * KPAD];
__device__ __align__(16) __nv_bfloat16 g_Whi[NPAD * KPAD];
__device__ __align__(16) __nv_bfloat16 g_Wlo[NPAD * KPAD];
__device__ __align__(16) __half g_embh[(size_t)NUM_NODES * HROW];

// ---------------- kernel 1: segment boundaries via binary search -------------
__global__ void k_bounds(const int* __restrict__ seg, int E) {
  int b = blockIdx.x * blockDim.x + threadIdx.x;
  if (b > BATCH) return;
  int lo = 0, hi = E;
  while (lo < hi) {
    int mid = (lo + hi) >> 1;
    if (seg[mid] < b) lo = mid + 1; else hi = mid;
  }
  g_seg_start[b] = lo;
}

// ---------------- kernel 1b: fp32 embeddings -> fp16 table (padded rows) -----
__global__ void k_h16(const float* __restrict__ emb) {
  int idx = blockIdx.x * blockDim.x + threadIdx.x;
  if (idx >= NUM_NODES * HROW) return;
  int node = idx / HROW;
  int col = idx - node * HROW;
  float v = (col < EMBED_DIM) ? __ldg(emb + (size_t)node * EMBED_DIM + col) : 0.f;
  g_embh[idx] = __float2half(v);
}

// split fp32 -> bf16 hi + bf16 lo (residual)
__device__ __forceinline__ void split_store(size_t idx, float x) {
  __nv_bfloat16 h = __float2bfloat16(x);
  g_Ahi[idx] = h;
  g_Alo[idx] = __float2bfloat16(x - __bfloat162float(h));
}

__device__ __forceinline__ void addh8(float* s, uint4 v) {
  const __half2* h = (const __half2*)&v;
#pragma unroll
  for (int q = 0; q < 4; q++) {
    float2 f = __half22float2(h[q]);
    s[q * 2] += f.x;
    s[q * 2 + 1] += f.y;
  }
}

// ---------------- kernel 2: fp16 gather + segment mean pool (1 warp/segment) -
__global__ __launch_bounds__(256) void k_pool(const int* __restrict__ nodes,
                                              const int* __restrict__ neighbors,
                                              const float* __restrict__ emb) {
  const int lane = threadIdx.x & 31;
  const int b = blockIdx.x * 8 + (threadIdx.x >> 5);
  const int n0 = __ldg(nodes + b);
  const bool selfA = n0 < NUM_AUTHOR;
  const int s = g_seg_start[b];
  const int e = g_seg_start[b + 1];
  const bool has2 = lane < 6;   // 38 uint4/row: lanes 0..5 own a second one

  float s1a[8], s1b[8], s2a[8], s2b[8];
#pragma unroll
  for (int j = 0; j < 8; j++) { s1a[j] = s1b[j] = s2a[j] = s2b[j] = 0.f; }
  float c1 = 0.f, c2 = 0.f;

  for (int i = s; i < e; i++) {
    int nb = __ldg(neighbors + i);
    bool same = (nb < NUM_AUTHOR) == selfA;
    const uint4* rp = (const uint4*)(g_embh + (size_t)nb * HROW);
    uint4 v0 = __ldg(rp + lane);
    uint4 v1 = make_uint4(0, 0, 0, 0);
    if (has2) v1 = __ldg(rp + 32 + lane);
    if (same) {
      c1 += 1.f;
      addh8(s1a, v0);
      if (has2) addh8(s1b, v1);
    } else {
      c2 += 1.f;
      addh8(s2a, v0);
      if (has2) addh8(s2b, v1);
    }
  }

  const size_t base = (size_t)b * KPAD;
  const float* srow = emb + (size_t)n0 * EMBED_DIM;

  // slot 0: dims 8*lane .. 8*lane+7 (all < 256 < 300)
#pragma unroll
  for (int j = 0; j < 8; j++) {
    int d = lane * 8 + j;
    float t1 = (c1 > 0.f) ? (s1a[j] / c1) : 1.0f;
    float t2 = (c2 > 0.f) ? (s2a[j] / c2) : 1.0f;
    split_store(base + d, __ldg(srow + d));
    split_store(base + 300 + d, t1);
    split_store(base + 600 + d, t2);
  }
  // slot 1: dims 256 + 8*lane .. (+7), lanes 0..5, guard d < 300
  if (has2) {
#pragma unroll
    for (int j = 0; j < 8; j++) {
      int d = 256 + lane * 8 + j;
      if (d < 300) {
        float t1 = (c1 > 0.f) ? (s1b[j] / c1) : 1.0f;
        float t2 = (c2 > 0.f) ? (s2b[j] / c2) : 1.0f;
        split_store(base + d, __ldg(srow + d));
        split_store(base + 300 + d, t1);
        split_store(base + 600 + d, t2);
      }
    }
  }
  // zero K-pad columns 900..959
  const __nv_bfloat16 z = __float2bfloat16(0.f);
  for (int d = 900 + lane; d < KPAD; d += 32) {
    g_Ahi[base + d] = z;
    g_Alo[base + d] = z;
  }
}

// ---------------- kernel 3: split + pad W1 into bf16 hi/lo -------------------
__global__ void k_wsplit(const float* __restrict__ W1) {
  int idx = blockIdx.x * blockDim.x + threadIdx.x;
  if (idx >= NPAD * KPAD) return;
  int n = idx / KPAD;
  int k = idx - n * KPAD;
  float w = (n < 300 && k < 900) ? __ldg(W1 + n * 900 + k) : 0.f;
  __nv_bfloat16 h = __float2bfloat16(w);
  g_Whi[idx] = h;
  g_Wlo[idx] = __float2bfloat16(w - __bfloat162float(h));
}

// ---------------- GEMM helpers ------------------------------------------------
__device__ __forceinline__ uint32_t s2u(const void* p) {
  return (uint32_t)__cvta_generic_to_shared(p);
}

__device__ __forceinline__ void cp16s(uint32_t sa, const void* g) {
  asm volatile("cp.async.cg.shared.global [%0], [%1], 16;\n" :: "r"(sa), "l"(g));
}

__device__ __forceinline__ void ldsm4(uint32_t a[4], uint32_t addr) {
  asm volatile("ldmatrix.sync.aligned.m8n8.x4.shared.b16 {%0,%1,%2,%3}, [%4];"
               : "=r"(a[0]), "=r"(a[1]), "=r"(a[2]), "=r"(a[3]) : "r"(addr));
}

__device__ __forceinline__ void ldsm2(uint32_t a[2], uint32_t addr) {
  asm volatile("ldmatrix.sync.aligned.m8n8.x2.shared.b16 {%0,%1}, [%2];"
               : "=r"(a[0]), "=r"(a[1]) : "r"(addr));
}

__device__ __forceinline__ void mma16816(float c[4], const uint32_t a[4],
                                         uint32_t b0, uint32_t b1) {
  asm volatile(
      "mma.sync.aligned.m16n8k16.row.col.f32.bf16.bf16.f32 "
      "{%0,%1,%2,%3},{%4,%5,%6,%7},{%8,%9},{%0,%1,%2,%3};\n"
      : "+f"(c[0]), "+f"(c[1]), "+f"(c[2]), "+f"(c[3])
      : "r"(a[0]), "r"(a[1]), "r"(a[2]), "r"(a[3]), "r"(b0), "r"(b1));
}

// ---------------- kernel 4: split-bf16 mma.sync GEMM, 512 threads ------------
// Block tile 128(M) x 160(N), K-chunk 64, 16 warps as 4(m) x 4(n),
// warp tile 32(m) x 40(n) -> 2 m16 x 5 n8, 3 split MMAs per tile.
// SW128-swizzled 128B smem rows; fragments via ldmatrix.
__global__ __launch_bounds__(512, 1) void k_gemm(const float* __restrict__ bias,
                                                 float* __restrict__ out) {
  extern __shared__ unsigned char sm_raw[];
  const int tid = threadIdx.x;
  const int lane = tid & 31;
  const int warp = tid >> 5;
  const int wm = warp >> 2;   // 0..3
  const int wn = warp & 3;    // 0..3
  const int m0 = blockIdx.x * 128;
  const int n0 = blockIdx.y * 160;

  const uint32_t base = (s2u(sm_raw) + 1023) & ~1023u;

  float acc[2][5][4];
#pragma unroll
  for (int i = 0; i < 2; i++)
#pragma unroll
    for (int j = 0; j < 5; j++)
#pragma unroll
      for (int k = 0; k < 4; k++) acc[i][j][k] = 0.f;

  const __nv_bfloat16* gAh = g_Ahi + (size_t)m0 * KPAD;
  const __nv_bfloat16* gAl = g_Alo + (size_t)m0 * KPAD;
  const __nv_bfloat16* gBh = g_Whi + (size_t)n0 * KPAD;
  const __nv_bfloat16* gBl = g_Wlo + (size_t)n0 * KPAD;

  // ldmatrix per-lane row/k-half mapping
  const int arow = lane & 15;              // A: rows 0..15 within m16 tile
  const int akh = (lane >> 4) * 16;        // A: k-half select
  const int brow = (lane & 7) + ((lane >> 4) << 3);  // B x4: 2 n8 tiles
  const int bkh = ((lane >> 3) & 1) * 16;

  auto load_stage = [&](int c, int st) {
    const uint32_t sb = base + st * ST_SIZE;
    const int koff = c * 64;
    for (int i = tid; i < 1024; i += 512) {   // A: 128 rows x 8 x 16B
      int row = i >> 3, kc = i & 7;
      int bo = row * 128 + kc * 16;
      int sw = bo ^ ((bo >> 3) & 0x70);
      size_t go = (size_t)row * KPAD + koff + kc * 8;
      cp16s(sb + ST_AHI + sw, gAh + go);
      cp16s(sb + ST_ALO + sw, gAl + go);
    }
    for (int i = tid; i < 1280; i += 512) {   // B: 160 rows x 8 x 16B
      int row = i >> 3, kc = i & 7;
      int bo = row * 128 + kc * 16;
      int sw = bo ^ ((bo >> 3) & 0x70);
      size_t go = (size_t)row * KPAD + koff + kc * 8;
      cp16s(sb + ST_BHI + sw, gBh + go);
      cp16s(sb + ST_BLO + sw, gBl + go);
    }
  };

  auto compute = [&](int st) {
    const uint32_t sb = base + st * ST_SIZE;
#pragma unroll
    for (int ks = 0; ks < 4; ks++) {
      uint32_t ah[2][4], al[2][4];
#pragma unroll
      for (int mi = 0; mi < 2; mi++) {
        int ra = wm * 32 + mi * 16 + arow;
        uint32_t off = ra * 128 + ((akh + ks * 32) ^ ((ra & 7) << 4));
        ldsm4(ah[mi], sb + ST_AHI + off);
        ldsm4(al[mi], sb + ST_ALO + off);
      }
      uint32_t bh[5][2], bl[5][2];
#pragma unroll
      for (int np = 0; np < 2; np++) {        // n8 tiles 0-3 via two x4
        int rb = wn * 40 + np * 16 + brow;
        uint32_t off = rb * 128 + ((bkh + ks * 32) ^ ((rb & 7) << 4));
        uint32_t t[4];
        ldsm4(t, sb + ST_BHI + off);
        bh[np * 2][0] = t[0]; bh[np * 2][1] = t[1];
        bh[np * 2 + 1][0] = t[2]; bh[np * 2 + 1][1] = t[3];
        ldsm4(t, sb + ST_BLO + off);
        bl[np * 2][0] = t[0]; bl[np * 2][1] = t[1];
        bl[np * 2 + 1][0] = t[2]; bl[np * 2 + 1][1] = t[3];
      }
      {                                        // n8 tile 4 via x2
        int rb = wn * 40 + 32 + (lane & 7);
        uint32_t off = rb * 128 + ((bkh + ks * 32) ^ ((rb & 7) << 4));
        uint32_t t[2];
        ldsm2(t, sb + ST_BHI + off);
        bh[4][0] = t[0]; bh[4][1] = t[1];
        ldsm2(t, sb + ST_BLO + off);
        bl[4][0] = t[0]; bl[4][1] = t[1];
      }
#pragma unroll
      for (int ni = 0; ni < 5; ni++)
#pragma unroll
        for (int mi = 0; mi < 2; mi++) {
          mma16816(acc[mi][ni], ah[mi], bh[ni][0], bh[ni][1]);   // hi*hi
          mma16816(acc[mi][ni], al[mi], bh[ni][0], bh[ni][1]);   // lo*hi
          mma16816(acc[mi][ni], ah[mi], bl[ni][0], bl[ni][1]);   // hi*lo
        }
    }
  };

  load_stage(0, 0);
  asm volatile("cp.async.commit_group;" ::: "memory");
  for (int c = 0; c < NCHUNK; c++) {
    if (c + 1 < NCHUNK) {
      load_stage(c + 1, (c + 1) & 1);
      asm volatile("cp.async.commit_group;" ::: "memory");
      asm volatile("cp.async.wait_group 1;" ::: "memory");
    } else {
      asm volatile("cp.async.wait_group 0;" ::: "memory");
    }
    __syncthreads();
    compute(c & 1);
    __syncthreads();
  }

  // epilogue: +bias, guard n<300 (pad columns dropped)
#pragma unroll
  for (int mi = 0; mi < 2; mi++) {
    int m = m0 + wm * 32 + mi * 16 + (lane >> 2);
#pragma unroll
    for (int ni = 0; ni < 5; ni++) {
      int n = n0 + wn * 40 + ni * 8 + (lane & 3) * 2;
      if (n < 300) {
        float bv0 = __ldg(bias + n);
        float bv1 = __ldg(bias + n + 1);
        float2 r0 = make_float2(acc[mi][ni][0] + bv0, acc[mi][ni][1] + bv1);
        float2 r1 = make_float2(acc[mi][ni][2] + bv0, acc[mi][ni][3] + bv1);
        *reinterpret_cast<float2*>(out + (size_t)m * 300 + n) = r0;
        *reinterpret_cast<float2*>(out + (size_t)(m + 8) * 300 + n) = r1;
      }
    }
  }
}

// ---------------- launch ------------------------------------------------------
extern "C" void kernel_launch(void* const* d_in, const int* in_sizes, int n_in,
                              void* d_out, int out_size) {
  const int* nodes     = (const int*)d_in[0];
  const int* seg       = (const int*)d_in[1];
  const int* neighbors = (const int*)d_in[2];
  const float* emb     = (const float*)d_in[3];
  const float* W1      = (const float*)d_in[4];
  const float* b1      = (const float*)d_in[5];
  float* out = (float*)d_out;
  const int E = in_sizes[1];

  const int smem = 1024 + 2 * ST_SIZE;   // 148480 B
  cudaFuncSetAttribute(k_gemm, cudaFuncAttributeMaxDynamicSharedMemorySize, smem);

  k_bounds<<<(BATCH + 1 + 255) / 256, 256>>>(seg, E);
  k_h16<<<(NUM_NODES * HROW + 255) / 256, 256>>>(emb);
  k_wsplit<<<(NPAD * KPAD + 255) / 256, 256>>>(W1);
  k_pool<<<BATCH / 8, 256>>>(nodes, neighbors, emb);
  k_gemm<<<dim3(BATCH / 128, NPAD / 160), 512, smem>>>(b1, out);
}

// round 9
// speedup vs baseline: 1.0098x; 1.0098x over previous
#include <cuda_runtime.h>
#include <cuda_bf16.h>
#include <cuda_fp16.h>
#include <cstdint>

#define NUM_AUTHOR 16604
#define NUM_NODES  29059
#define EMBED_DIM  300
#define BATCH      32768
#define KPAD       960        // 900 padded to 15 chunks of 64
#define NPAD       320        // 300 padded
#define NCHUNK     15
#define HROW       304        // fp16 table row stride (38 x uint4)

// stage byte offsets (SW128 swizzled, 128B rows, all 1024-aligned)
#define ST_AHI 0              // 128 x 128B = 16384
#define ST_ALO 16384
#define ST_BHI 32768          // 160 x 128B = 20480
#define ST_BLO 53248
#define ST_SIZE 73728         // 72 KB per stage

// ---------------- device scratch (allocation-free rule: __device__ globals) ---
__device__ int g_seg_start[BATCH + 1];
__device__ __align__(16) __nv_bfloat16 g_Ahi[(size_t)BATCH * KPAD];
__device__ __align__(16) __nv_bfloat16 g_Alo[(size_t)BATCH * KPAD];
__device__ __align__(16) __nv_bfloat16 g_Whi[NPAD * KPAD];
__device__ __align__(16) __nv_bfloat16 g_Wlo[NPAD * KPAD];
__device__ __align__(16) __half g_embh[(size_t)NUM_NODES * HROW];

// ---------------- kernel 1: segment boundaries via binary search -------------
__global__ void k_bounds(const int* __restrict__ seg, int E) {
  int b = blockIdx.x * blockDim.x + threadIdx.x;
  if (b > BATCH) return;
  int lo = 0, hi = E;
  while (lo < hi) {
    int mid = (lo + hi) >> 1;
    if (seg[mid] < b) lo = mid + 1; else hi = mid;
  }
  g_seg_start[b] = lo;
}

// ---------------- kernel 1b: fp32 embeddings -> fp16 table (padded rows) -----
__global__ void k_h16(const float* __restrict__ emb) {
  int idx = blockIdx.x * blockDim.x + threadIdx.x;
  if (idx >= NUM_NODES * HROW) return;
  int node = idx / HROW;
  int col = idx - node * HROW;
  float v = (col < EMBED_DIM) ? __ldg(emb + (size_t)node * EMBED_DIM + col) : 0.f;
  g_embh[idx] = __float2half(v);
}

// split fp32 -> bf16 hi + bf16 lo (residual)
__device__ __forceinline__ void split_store(size_t idx, float x) {
  __nv_bfloat16 h = __float2bfloat16(x);
  g_Ahi[idx] = h;
  g_Alo[idx] = __float2bfloat16(x - __bfloat162float(h));
}

__device__ __forceinline__ void addh8(float* s, uint4 v) {
  const __half2* h = (const __half2*)&v;
#pragma unroll
  for (int q = 0; q < 4; q++) {
    float2 f = __half22float2(h[q]);
    s[q * 2] += f.x;
    s[q * 2 + 1] += f.y;
  }
}

// ---------------- kernel 2: fp16 gather + segment mean pool (1 warp/segment) -
__global__ __launch_bounds__(256) void k_pool(const int* __restrict__ nodes,
                                              const int* __restrict__ neighbors,
                                              const float* __restrict__ emb) {
  const int lane = threadIdx.x & 31;
  const int b = blockIdx.x * 8 + (threadIdx.x >> 5);
  const int n0 = __ldg(nodes + b);
  const bool selfA = n0 < NUM_AUTHOR;
  const int s = g_seg_start[b];
  const int e = g_seg_start[b + 1];
  const bool has2 = lane < 6;   // 38 uint4/row: lanes 0..5 own a second one

  float s1a[8], s1b[8], s2a[8], s2b[8];
#pragma unroll
  for (int j = 0; j < 8; j++) { s1a[j] = s1b[j] = s2a[j] = s2b[j] = 0.f; }
  float c1 = 0.f, c2 = 0.f;

  for (int i = s; i < e; i++) {
    int nb = __ldg(neighbors + i);
    bool same = (nb < NUM_AUTHOR) == selfA;
    const uint4* rp = (const uint4*)(g_embh + (size_t)nb * HROW);
    uint4 v0 = __ldg(rp + lane);
    uint4 v1 = make_uint4(0, 0, 0, 0);
    if (has2) v1 = __ldg(rp + 32 + lane);
    if (same) {
      c1 += 1.f;
      addh8(s1a, v0);
      if (has2) addh8(s1b, v1);
    } else {
      c2 += 1.f;
      addh8(s2a, v0);
      if (has2) addh8(s2b, v1);
    }
  }

  const size_t base = (size_t)b * KPAD;
  const float* srow = emb + (size_t)n0 * EMBED_DIM;

  // slot 0: dims 8*lane .. 8*lane+7 (all < 256 < 300)
#pragma unroll
  for (int j = 0; j < 8; j++) {
    int d = lane * 8 + j;
    float t1 = (c1 > 0.f) ? (s1a[j] / c1) : 1.0f;
    float t2 = (c2 > 0.f) ? (s2a[j] / c2) : 1.0f;
    split_store(base + d, __ldg(srow + d));
    split_store(base + 300 + d, t1);
    split_store(base + 600 + d, t2);
  }
  // slot 1: dims 256 + 8*lane .. (+7), lanes 0..5, guard d < 300
  if (has2) {
#pragma unroll
    for (int j = 0; j < 8; j++) {
      int d = 256 + lane * 8 + j;
      if (d < 300) {
        float t1 = (c1 > 0.f) ? (s1b[j] / c1) : 1.0f;
        float t2 = (c2 > 0.f) ? (s2b[j] / c2) : 1.0f;
        split_store(base + d, __ldg(srow + d));
        split_store(base + 300 + d, t1);
        split_store(base + 600 + d, t2);
      }
    }
  }
  // zero K-pad columns 900..959
  const __nv_bfloat16 z = __float2bfloat16(0.f);
  for (int d = 900 + lane; d < KPAD; d += 32) {
    g_Ahi[base + d] = z;
    g_Alo[base + d] = z;
  }
}

// ---------------- kernel 3: split + pad W1 into bf16 hi/lo -------------------
__global__ void k_wsplit(const float* __restrict__ W1) {
  int idx = blockIdx.x * blockDim.x + threadIdx.x;
  if (idx >= NPAD * KPAD) return;
  int n = idx / KPAD;
  int k = idx - n * KPAD;
  float w = (n < 300 && k < 900) ? __ldg(W1 + n * 900 + k) : 0.f;
  __nv_bfloat16 h = __float2bfloat16(w);
  g_Whi[idx] = h;
  g_Wlo[idx] = __float2bfloat16(w - __bfloat162float(h));
}

// ---------------- GEMM helpers ------------------------------------------------
__device__ __forceinline__ uint32_t s2u(const void* p) {
  return (uint32_t)__cvta_generic_to_shared(p);
}

__device__ __forceinline__ void cp16s(uint32_t sa, const void* g) {
  asm volatile("cp.async.cg.shared.global [%0], [%1], 16;\n" :: "r"(sa), "l"(g));
}

__device__ __forceinline__ void ldsm4(uint32_t a[4], uint32_t addr) {
  asm volatile("ldmatrix.sync.aligned.m8n8.x4.shared.b16 {%0,%1,%2,%3}, [%4];"
               : "=r"(a[0]), "=r"(a[1]), "=r"(a[2]), "=r"(a[3]) : "r"(addr));
}

__device__ __forceinline__ void ldsm2(uint32_t a[2], uint32_t addr) {
  asm volatile("ldmatrix.sync.aligned.m8n8.x2.shared.b16 {%0,%1}, [%2];"
               : "=r"(a[0]), "=r"(a[1]) : "r"(addr));
}

__device__ __forceinline__ void mma16816(float c[4], const uint32_t a[4],
                                         uint32_t b0, uint32_t b1) {
  asm volatile(
      "mma.sync.aligned.m16n8k16.row.col.f32.bf16.bf16.f32 "
      "{%0,%1,%2,%3},{%4,%5,%6,%7},{%8,%9},{%0,%1,%2,%3};\n"
      : "+f"(c[0]), "+f"(c[1]), "+f"(c[2]), "+f"(c[3])
      : "r"(a[0]), "r"(a[1]), "r"(a[2]), "r"(a[3]), "r"(b0), "r"(b1));
}

// ---------------- kernel 4: split-bf16 mma.sync GEMM, 512 threads ------------
// Block tile 128(M) x 160(N), K-chunk 64, 16 warps as 4(m) x 4(n),
// warp tile 32(m) x 40(n) -> 2 m16 x 5 n8, 3 split MMAs per tile.
// SW128-swizzled 128B smem rows; fragments via ldmatrix.
__global__ __launch_bounds__(512, 1) void k_gemm(const float* __restrict__ bias,
                                                 float* __restrict__ out) {
  extern __shared__ unsigned char sm_raw[];
  const int tid = threadIdx.x;
  const int lane = tid & 31;
  const int warp = tid >> 5;
  const int wm = warp >> 2;   // 0..3
  const int wn = warp & 3;    // 0..3
  const int m0 = blockIdx.x * 128;
  const int n0 = blockIdx.y * 160;

  const uint32_t base = (s2u(sm_raw) + 1023) & ~1023u;

  float acc[2][5][4];
#pragma unroll
  for (int i = 0; i < 2; i++)
#pragma unroll
    for (int j = 0; j < 5; j++)
#pragma unroll
      for (int k = 0; k < 4; k++) acc[i][j][k] = 0.f;

  const __nv_bfloat16* gAh = g_Ahi + (size_t)m0 * KPAD;
  const __nv_bfloat16* gAl = g_Alo + (size_t)m0 * KPAD;
  const __nv_bfloat16* gBh = g_Whi + (size_t)n0 * KPAD;
  const __nv_bfloat16* gBl = g_Wlo + (size_t)n0 * KPAD;

  // ldmatrix per-lane row/k-half mapping
  const int arow = lane & 15;              // A: rows 0..15 within m16 tile
  const int akh = (lane >> 4) * 16;        // A: k-half select
  const int brow = (lane & 7) + ((lane >> 4) << 3);  // B x4: 2 n8 tiles
  const int bkh = ((lane >> 3) & 1) * 16;

  auto load_stage = [&](int c, int st) {
    const uint32_t sb = base + st * ST_SIZE;
    const int koff = c * 64;
    for (int i = tid; i < 1024; i += 512) {   // A: 128 rows x 8 x 16B
      int row = i >> 3, kc = i & 7;
      int bo = row * 128 + kc * 16;
      int sw = bo ^ ((bo >> 3) & 0x70);
      size_t go = (size_t)row * KPAD + koff + kc * 8;
      cp16s(sb + ST_AHI + sw, gAh + go);
      cp16s(sb + ST_ALO + sw, gAl + go);
    }
    for (int i = tid; i < 1280; i += 512) {   // B: 160 rows x 8 x 16B
      int row = i >> 3, kc = i & 7;
      int bo = row * 128 + kc * 16;
      int sw = bo ^ ((bo >> 3) & 0x70);
      size_t go = (size_t)row * KPAD + koff + kc * 8;
      cp16s(sb + ST_BHI + sw, gBh + go);
      cp16s(sb + ST_BLO + sw, gBl + go);
    }
  };

  auto compute = [&](int st) {
    const uint32_t sb = base + st * ST_SIZE;
#pragma unroll
    for (int ks = 0; ks < 4; ks++) {
      uint32_t ah[2][4], al[2][4];
#pragma unroll
      for (int mi = 0; mi < 2; mi++) {
        int ra = wm * 32 + mi * 16 + arow;
        uint32_t off = ra * 128 + ((akh + ks * 32) ^ ((ra & 7) << 4));
        ldsm4(ah[mi], sb + ST_AHI + off);
        ldsm4(al[mi], sb + ST_ALO + off);
      }
      uint32_t bh[5][2], bl[5][2];
#pragma unroll
      for (int np = 0; np < 2; np++) {        // n8 tiles 0-3 via two x4
        int rb = wn * 40 + np * 16 + brow;
        uint32_t off = rb * 128 + ((bkh + ks * 32) ^ ((rb & 7) << 4));
        uint32_t t[4];
        ldsm4(t, sb + ST_BHI + off);
        bh[np * 2][0] = t[0]; bh[np * 2][1] = t[1];
        bh[np * 2 + 1][0] = t[2]; bh[np * 2 + 1][1] = t[3];
        ldsm4(t, sb + ST_BLO + off);
        bl[np * 2][0] = t[0]; bl[np * 2][1] = t[1];
        bl[np * 2 + 1][0] = t[2]; bl[np * 2 + 1][1] = t[3];
      }
      {                                        // n8 tile 4 via x2
        int rb = wn * 40 + 32 + (lane & 7);
        uint32_t off = rb * 128 + ((bkh + ks * 32) ^ ((rb & 7) << 4));
        uint32_t t[2];
        ldsm2(t, sb + ST_BHI + off);
        bh[4][0] = t[0]; bh[4][1] = t[1];
        ldsm2(t, sb + ST_BLO + off);
        bl[4][0] = t[0]; bl[4][1] = t[1];
      }
#pragma unroll
      for (int ni = 0; ni < 5; ni++)
#pragma unroll
        for (int mi = 0; mi < 2; mi++) {
          mma16816(acc[mi][ni], ah[mi], bh[ni][0], bh[ni][1]);   // hi*hi
          mma16816(acc[mi][ni], al[mi], bh[ni][0], bh[ni][1]);   // lo*hi
          mma16816(acc[mi][ni], ah[mi], bl[ni][0], bl[ni][1]);   // hi*lo
        }
    }
  };

  load_stage(0, 0);
  asm volatile("cp.async.commit_group;" ::: "memory");
  for (int c = 0; c < NCHUNK; c++) {
    if (c + 1 < NCHUNK) {
      load_stage(c + 1, (c + 1) & 1);
      asm volatile("cp.async.commit_group;" ::: "memory");
      asm volatile("cp.async.wait_group 1;" ::: "memory");
    } else {
      asm volatile("cp.async.wait_group 0;" ::: "memory");
    }
    __syncthreads();
    compute(c & 1);
    __syncthreads();
  }

  // epilogue: +bias, guard n<300 (pad columns dropped)
#pragma unroll
  for (int mi = 0; mi < 2; mi++) {
    int m = m0 + wm * 32 + mi * 16 + (lane >> 2);
#pragma unroll
    for (int ni = 0; ni < 5; ni++) {
      int n = n0 + wn * 40 + ni * 8 + (lane & 3) * 2;
      if (n < 300) {
        float bv0 = __ldg(bias + n);
        float bv1 = __ldg(bias + n + 1);
        float2 r0 = make_float2(acc[mi][ni][0] + bv0, acc[mi][ni][1] + bv1);
        float2 r1 = make_float2(acc[mi][ni][2] + bv0, acc[mi][ni][3] + bv1);
        *reinterpret_cast<float2*>(out + (size_t)m * 300 + n) = r0;
        *reinterpret_cast<float2*>(out + (size_t)(m + 8) * 300 + n) = r1;
      }
    }
  }
}

// ---------------- launch ------------------------------------------------------
extern "C" void kernel_launch(void* const* d_in, const int* in_sizes, int n_in,
                              void* d_out, int out_size) {
  const int* nodes     = (const int*)d_in[0];
  const int* seg       = (const int*)d_in[1];
  const int* neighbors = (const int*)d_in[2];
  const float* emb     = (const float*)d_in[3];
  const float* W1      = (const float*)d_in[4];
  const float* b1      = (const float*)d_in[5];
  float* out = (float*)d_out;
  const int E = in_sizes[1];

  const int smem = 1024 + 2 * ST_SIZE;   // 148480 B
  cudaFuncSetAttribute(k_gemm, cudaFuncAttributeMaxDynamicSharedMemorySize, smem);

  k_bounds<<<(BATCH + 1 + 255) / 256, 256>>>(seg, E);
  k_h16<<<(NUM_NODES * HROW + 255) / 256, 256>>>(emb);
  k_wsplit<<<(NPAD * KPAD + 255) / 256, 256>>>(W1);
  k_pool<<<BATCH / 8, 256>>>(nodes, neighbors, emb);
  k_gemm<<<dim3(BATCH / 128, NPAD / 160), 512, smem>>>(b1, out);
}